// round 14
// baseline (speedup 1.0000x reference)
#include <cuda_runtime.h>
#include <math.h>

#define T_LEN   2000000
#define NTAGS   5
#define START_T 3
#define STOP_T  4
#define LN2_D   0.6931471805599453

#define NB      608                   // 4 blocks/SM x 152 SMs — all co-resident
#define SEG     7                     // steps per segment
#define CPT2    14                    // steps per thread (2 segments)
#define SPB     (256 * CPT2)          // 3584 steps per block
#define GPB     (SPB / 4)             // 896 4-row groups per block
#define NGRP    500000
#define SSTR    15                    // smem stride (odd -> conflict-free)
#define SEG_LAST 285714               // last active segment: 1 + 7*285714 = 1999999

__device__ float    g_Mblk[NB][9];
__device__ int      g_Bblk[NB];
__device__ float    g_goldB[NB];
__device__ double   g_partB[NB];
__device__ float    g_stop3[3];
__device__ unsigned g_bar, g_tick;

__device__ __forceinline__ void renorm9(float* P, int& base) {
    float m = fmaxf(fmaxf(fmaxf(P[0], P[1]), fmaxf(P[2], P[3])),
                    fmaxf(fmaxf(P[4], P[5]), fmaxf(P[6], fmaxf(P[7], P[8]))));
    int e = (int)(__float_as_uint(m) >> 23) - 127;
    float sc = __uint_as_float((unsigned)(127 - e) << 23);
#pragma unroll
    for (int i = 0; i < 9; ++i) P[i] *= sc;
    base += e;
}

__device__ __forceinline__ void mm9(const float* Bm, const float* A, float* C) {
#pragma unroll
    for (int i = 0; i < 3; ++i)
#pragma unroll
        for (int j = 0; j < 3; ++j)
            C[i*3+j] = Bm[i*3+0]*A[0+j] + Bm[i*3+1]*A[3+j] + Bm[i*3+2]*A[6+j];
}

#define MATSTEP(P, F0, F1, F2) do {                                          \
    float e0 = exp2f(L2E*(F0)), e1 = exp2f(L2E*(F1)), e2 = exp2f(L2E*(F2));  \
    float a0 = e0*Tl[0], a1 = e0*Tl[1], a2 = e0*Tl[2];                       \
    float b0 = e1*Tl[3], b1 = e1*Tl[4], b2 = e1*Tl[5];                       \
    float d0 = e2*Tl[6], d1 = e2*Tl[7], d2 = e2*Tl[8];                       \
    float q0 = a0*P[0] + a1*P[3] + a2*P[6];                                  \
    float q1 = a0*P[1] + a1*P[4] + a2*P[7];                                  \
    float q2 = a0*P[2] + a1*P[5] + a2*P[8];                                  \
    float q3 = b0*P[0] + b1*P[3] + b2*P[6];                                  \
    float q4 = b0*P[1] + b1*P[4] + b2*P[7];                                  \
    float q5 = b0*P[2] + b1*P[5] + b2*P[8];                                  \
    float q6 = d0*P[0] + d1*P[3] + d2*P[6];                                  \
    float q7 = d0*P[1] + d1*P[4] + d2*P[7];                                  \
    float q8 = d0*P[2] + d1*P[5] + d2*P[8];                                  \
    P[0]=q0;P[1]=q1;P[2]=q2;P[3]=q3;P[4]=q4;P[5]=q5;P[6]=q6;P[7]=q7;P[8]=q8; \
} while (0)

#define EMSTEP(v0_, v1_, v2_, F0, F1, F2) do {                               \
    float f0 = (F0), f1 = (F1), f2 = (F2);                                   \
    float a00=__fadd_rn(v0_,t00), a01=__fadd_rn(v1_,t01), a02=__fadd_rn(v2_,t02);\
    float a10=__fadd_rn(v0_,t10), a11=__fadd_rn(v1_,t11), a12=__fadd_rn(v2_,t12);\
    float a20=__fadd_rn(v0_,t20), a21=__fadd_rn(v1_,t21), a22=__fadd_rn(v2_,t22);\
    float m0=fmaxf(fmaxf(a00,a01),a02);                                      \
    float m1=fmaxf(fmaxf(a10,a11),a12);                                      \
    float m2=fmaxf(fmaxf(a20,a21),a22);                                      \
    float s0=__expf(a00-m0)+__expf(a01-m0)+__expf(a02-m0);                   \
    float s1=__expf(a10-m1)+__expf(a11-m1)+__expf(a12-m1);                   \
    float s2=__expf(a20-m2)+__expf(a21-m2)+__expf(a22-m2);                   \
    v0_=__fadd_rn(__fadd_rn(__logf(s0),m0),f0);                              \
    v1_=__fadd_rn(__fadd_rn(__logf(s1),m1),f1);                              \
    v2_=__fadd_rn(__fadd_rn(__logf(s2),m2),f2);                              \
} while (0)

__global__ void __launch_bounds__(256, 4) crf_fused(
        const float* __restrict__ feats, const int* __restrict__ tags,
        const float* __restrict__ trans, float* __restrict__ out) {
    __shared__ float  sF0[256 * SSTR];
    __shared__ float  sF1[256 * SSTR];
    __shared__ float  sF2[256 * SSTR];
    __shared__ float  sTr[25];
    __shared__ float  sT9[8][9]; __shared__ int sbT[8];
    __shared__ float  sWE[8][9]; __shared__ int sbWE[8];
    __shared__ float  sEb9[9];   __shared__ int sEbB;
    __shared__ double sRD[8];
    __shared__ double sRD2[8];
    __shared__ float  sRF[8];
    __shared__ bool   sLast;

    const float L2E = 1.4426950408889634f;
    int tid = threadIdx.x, lane = tid & 31, wid = tid >> 5, bid = blockIdx.x;
    if (tid < 25) sTr[tid] = trans[tid];
    __syncthreads();

    float Tl[9];
#pragma unroll
    for (int i = 0; i < 3; ++i)
#pragma unroll
        for (int k = 0; k < 3; ++k)
            Tl[i*3+k] = exp2f(L2E * sTr[i * NTAGS + k]);

    // ================= Phase A: coalesced load -> smem + fused gold =================
    float gold = 0.f;
#pragma unroll
    for (int it = 0; it < 4; ++it) {
        int Gl = it * 256 + tid;
        if (Gl < GPB) {
            int G = bid * GPB + Gl;
            if (G < NGRP) {
                const float4* fp = (const float4*)feats;
                int q = 5 * G + 1;
                float4 v0, v1, v2, v3, v4;
                if (G < NGRP - 1) {
                    v0 = fp[q];     v1 = fp[q + 1]; v2 = fp[q + 2];
                    v3 = fp[q + 3]; v4 = fp[q + 4];
                } else {
                    v0 = fp[q];     v1 = fp[q + 1]; v2 = fp[q + 2]; v3 = fp[q + 3];
                    v4 = make_float4(0.f, 0.f, 0.f, 0.f);
                }
                float w0[4] = {v0.y, v1.z, v2.w, v4.x};
                float w1[4] = {v0.z, v1.w, v3.x, v4.y};
                float w2[4] = {v0.w, v2.x, v3.y, v4.z};

                int4 tg = ((const int4*)tags)[G];
                bool r3v = (4 * G + 4 < T_LEN);
                int tg4 = r3v ? __ldg(&tags[4 * G + 4]) : 0;
                int prev = tg.x, cur;
                cur = tg.y; gold += ((cur==0)?w0[0]:(cur==1)?w1[0]:w2[0]) + sTr[cur*5+prev]; prev = cur;
                cur = tg.z; gold += ((cur==0)?w0[1]:(cur==1)?w1[1]:w2[1]) + sTr[cur*5+prev]; prev = cur;
                cur = tg.w; gold += ((cur==0)?w0[2]:(cur==1)?w1[2]:w2[2]) + sTr[cur*5+prev]; prev = cur;
                if (r3v) {
                    cur = tg4; gold += ((cur==0)?w0[3]:(cur==1)?w1[3]:w2[3]) + sTr[cur*5+prev];
                }
#pragma unroll
                for (int r = 0; r < 4; ++r) {
                    int o = 4 * Gl + r;
                    int ln = o / CPT2, s = o - CPT2 * ln;
                    int a = ln * SSTR + s;
                    sF0[a] = w0[r]; sF1[a] = w1[r]; sF2[a] = w2[r];
                }
            }
        }
    }
#pragma unroll
    for (int o = 16; o > 0; o >>= 1) gold += __shfl_down_sync(0xFFFFFFFFu, gold, o);
    if (lane == 0) sRF[wid] = gold;
    __syncthreads();                           // also publishes sF*
    if (tid == 0) {
        float gg = 0.f;
        for (int k = 0; k < 8; ++k) gg += sRF[k];
        g_goldB[bid] = gg;
    }

    // ================= MAT: two independent 7-step chains (ILP-2) =================
    int gt = bid * 256 + tid;                  // global thread
    int segA = 2 * gt;                         // segments owned
    int startA = 1 + segA * SEG;
    int nA = T_LEN - startA;          nA = nA < 0 ? 0 : (nA > SEG ? SEG : nA);
    int nB = T_LEN - (startA + SEG);  nB = nB < 0 ? 0 : (nB > SEG ? SEG : nB);
    int sb0 = tid * SSTR;

    float Pa[9] = {1.f,0.f,0.f, 0.f,1.f,0.f, 0.f,0.f,1.f};
    float Pc[9] = {1.f,0.f,0.f, 0.f,1.f,0.f, 0.f,0.f,1.f};  // segment B matrix, then scan
    int baseA = 0, base = 0;
    if (nB == SEG) {                            // both segments full (hot path)
#pragma unroll
        for (int s = 0; s < SEG; ++s) {
            MATSTEP(Pa, sF0[sb0+s],     sF1[sb0+s],     sF2[sb0+s]);
            MATSTEP(Pc, sF0[sb0+SEG+s], sF1[sb0+SEG+s], sF2[sb0+SEG+s]);
        }
    } else {
        for (int s = 0; s < nA; ++s) MATSTEP(Pa, sF0[sb0+s], sF1[sb0+s], sF2[sb0+s]);
        for (int s = 0; s < nB; ++s) MATSTEP(Pc, sF0[sb0+SEG+s], sF1[sb0+SEG+s], sF2[sb0+SEG+s]);
    }
    renorm9(Pa, baseA);
    renorm9(Pc, base);
    {   // thread total = Pb x Pa (later x earlier)
        float C[9];
        mm9(Pc, Pa, C);
        base += baseA;
        renorm9(C, base);
#pragma unroll
        for (int i = 0; i < 9; ++i) Pc[i] = C[i];
    }

    // warp Kogge-Stone inclusive scan of thread totals; renorm at end only
#pragma unroll
    for (int s = 1; s < 32; s <<= 1) {
        float A[9];
#pragma unroll
        for (int i = 0; i < 9; ++i) A[i] = __shfl_up_sync(0xFFFFFFFFu, Pc[i], s);
        int ab = __shfl_up_sync(0xFFFFFFFFu, base, s);
        if (lane >= s) {
            float C[9];
            mm9(Pc, A, C);
            base += ab;
#pragma unroll
            for (int i = 0; i < 9; ++i) Pc[i] = C[i];
        }
    }
    renorm9(Pc, base);
    if (lane == 31) {
#pragma unroll
        for (int i = 0; i < 9; ++i) sT9[wid][i] = Pc[i];
        sbT[wid] = base;
    }
    __syncthreads();
    if (tid < 8) {
        float E[9] = {1.f,0.f,0.f, 0.f,1.f,0.f, 0.f,0.f,1.f};
        int be = 0;
        for (int k = 0; k < tid; ++k) {
            float Tk[9], C[9];
#pragma unroll
            for (int i = 0; i < 9; ++i) Tk[i] = sT9[k][i];
            mm9(Tk, E, C);
            be += sbT[k];
#pragma unroll
            for (int i = 0; i < 9; ++i) E[i] = C[i];
        }
        renorm9(E, be);
#pragma unroll
        for (int i = 0; i < 9; ++i) sWE[tid][i] = E[i];
        sbWE[tid] = be;
    }
    __syncthreads();

    if (tid == 255) {                           // block total
        float W[9], C[9];
#pragma unroll
        for (int i = 0; i < 9; ++i) W[i] = sWE[wid][i];
        mm9(Pc, W, C);
        int bb = base + sbWE[wid];
        renorm9(C, bb);
#pragma unroll
        for (int i = 0; i < 9; ++i) g_Mblk[bid][i] = C[i];
        g_Bblk[bid] = bb;
    }

    // ================= global barrier (all 608 blocks co-resident) =================
    __syncthreads();
    if (tid == 0) {
        __threadfence();
        atomicAdd(&g_bar, 1u);
        while (*((volatile unsigned*)&g_bar) < (unsigned)NB) __nanosleep(64);
    }
    __syncthreads();
    __threadfence();

    // ===== block-exclusive prefix Eb: block-wide ordered reduction over [0, bid) =====
    {
        float E[9] = {1.f,0.f,0.f, 0.f,1.f,0.f, 0.f,0.f,1.f};
        int be = 0;
#pragma unroll
        for (int k = 0; k < 3; ++k) {
            int i = tid * 3 + k;
            if (i < bid) {
                float M[9], C[9];
#pragma unroll
                for (int j = 0; j < 9; ++j) M[j] = g_Mblk[i][j];
                mm9(M, E, C);
                be += g_Bblk[i];
#pragma unroll
                for (int j = 0; j < 9; ++j) E[j] = C[j];
            }
        }
        renorm9(E, be);
#pragma unroll
        for (int o = 1; o < 32; o <<= 1) {
            float R[9];
#pragma unroll
            for (int j = 0; j < 9; ++j) R[j] = __shfl_down_sync(0xFFFFFFFFu, E[j], o);
            int rb = __shfl_down_sync(0xFFFFFFFFu, be, o);
            float C[9];
            mm9(R, E, C);
            be += rb;
            renorm9(C, be);
#pragma unroll
            for (int j = 0; j < 9; ++j) E[j] = C[j];
        }
        if (lane == 0) {
#pragma unroll
            for (int j = 0; j < 9; ++j) sT9[wid][j] = E[j];
            sbT[wid] = be;
        }
    }
    __syncthreads();
    if (tid == 0) {
        float E[9] = {1.f,0.f,0.f, 0.f,1.f,0.f, 0.f,0.f,1.f};
        int be = 0;
        for (int w = 0; w < 8; ++w) {
            float Tk[9], C[9];
#pragma unroll
            for (int j = 0; j < 9; ++j) Tk[j] = sT9[w][j];
            mm9(Tk, E, C);
            be += sbT[w];
            renorm9(C, be);
#pragma unroll
            for (int j = 0; j < 9; ++j) E[j] = C[j];
        }
#pragma unroll
        for (int j = 0; j < 9; ++j) sEb9[j] = E[j];
        sEbB = be;
    }
    __syncthreads();

    // ================= boundaries (registers) =================
    float v00 = sTr[0*NTAGS+START_T] + __ldg(&feats[0]);
    float v01 = sTr[1*NTAGS+START_T] + __ldg(&feats[1]);
    float v02 = sTr[2*NTAGS+START_T] + __ldg(&feats[2]);
    float c0f = fmaxf(fmaxf(v00, v01), v02);
    double c0d = (double)c0f;
    float u0[3] = {__expf(v00-c0f), __expf(v01-c0f), __expf(v02-c0f)};

    // W2 = warp-exclusive x block-exclusive
    float W2[9]; int bW2;
    {
        float Eb[9];
#pragma unroll
        for (int j = 0; j < 9; ++j) Eb[j] = sEb9[j];
        float W[9];
#pragma unroll
        for (int j = 0; j < 9; ++j) W[j] = sWE[wid][j];
        mm9(W, Eb, W2);
        bW2 = sbWE[wid] + sEbB;
        renorm9(W2, bW2);
    }
    // thread-exclusive (warp-local) = shfl of scanned inclusive
    float Lx[9]; int bLx;
#pragma unroll
    for (int j = 0; j < 9; ++j) Lx[j] = __shfl_up_sync(0xFFFFFFFFu, Pc[j], 1);
    bLx = __shfl_up_sync(0xFFFFFFFFu, base, 1);
    if (lane == 0) {
#pragma unroll
        for (int j = 0; j < 9; ++j) Lx[j] = (j % 4 == 0) ? 1.f : 0.f;
        bLx = 0;
    }

    // BnA = boundary after segment A; BnB = after segment B
    float BnA0, BnA1, BnA2, BnB0, BnB1, BnB2;
    {
        float MA[9]; int bMA = baseA + bLx;
        mm9(Pa, Lx, MA);
        float GA[9]; int bGA = bMA + bW2;
        mm9(MA, W2, GA);
        renorm9(GA, bGA);
        double tA = (double)bGA * LN2_D + c0d;
        BnA0 = (float)((double)__logf(GA[0]*u0[0] + GA[1]*u0[1] + GA[2]*u0[2]) + tA);
        BnA1 = (float)((double)__logf(GA[3]*u0[0] + GA[4]*u0[1] + GA[5]*u0[2]) + tA);
        BnA2 = (float)((double)__logf(GA[6]*u0[0] + GA[7]*u0[1] + GA[8]*u0[2]) + tA);

        float GB[9]; int bGB = base + bW2;
        mm9(Pc, W2, GB);
        renorm9(GB, bGB);
        double tB = (double)bGB * LN2_D + c0d;
        BnB0 = (float)((double)__logf(GB[0]*u0[0] + GB[1]*u0[1] + GB[2]*u0[2]) + tB);
        BnB1 = (float)((double)__logf(GB[3]*u0[0] + GB[4]*u0[1] + GB[5]*u0[2]) + tB);
        BnB2 = (float)((double)__logf(GB[6]*u0[0] + GB[7]*u0[1] + GB[8]*u0[2]) + tB);
    }

    // aA = previous thread's BnB (bit-identical via shfl); lane 0 from W2
    float A0 = __shfl_up_sync(0xFFFFFFFFu, BnB0, 1);
    float A1 = __shfl_up_sync(0xFFFFFFFFu, BnB1, 1);
    float A2 = __shfl_up_sync(0xFFFFFFFFu, BnB2, 1);
    if (lane == 0) {
        if (bid == 0 && tid == 0) {
            A0 = v00; A1 = v01; A2 = v02;
        } else {
            double tX = (double)bW2 * LN2_D + c0d;
            A0 = (float)((double)__logf(W2[0]*u0[0] + W2[1]*u0[1] + W2[2]*u0[2]) + tX);
            A1 = (float)((double)__logf(W2[3]*u0[0] + W2[4]*u0[1] + W2[5]*u0[2]) + tX);
            A2 = (float)((double)__logf(W2[6]*u0[0] + W2[7]*u0[1] + W2[8]*u0[2]) + tX);
        }
    }

    // ================= emulation: two independent 7-step walks (ILP-2) ============
    float t00 = sTr[0],  t01 = sTr[1],  t02 = sTr[2];
    float t10 = sTr[5],  t11 = sTr[6],  t12 = sTr[7];
    float t20 = sTr[10], t21 = sTr[11], t22 = sTr[12];

    float fa0 = A0,   fa1 = A1,   fa2 = A2;     // segment A starts at aA
    float fb0 = BnA0, fb1 = BnA1, fb2 = BnA2;   // segment B starts at BnA (exact telescope)

    if (nB == SEG) {
#pragma unroll
        for (int s = 0; s < SEG; ++s) {
            EMSTEP(fa0, fa1, fa2, sF0[sb0+s],     sF1[sb0+s],     sF2[sb0+s]);
            EMSTEP(fb0, fb1, fb2, sF0[sb0+SEG+s], sF1[sb0+SEG+s], sF2[sb0+SEG+s]);
        }
    } else {
        for (int s = 0; s < nA; ++s)
            EMSTEP(fa0, fa1, fa2, sF0[sb0+s], sF1[sb0+s], sF2[sb0+s]);
        for (int s = 0; s < nB; ++s)
            EMSTEP(fb0, fb1, fb2, sF0[sb0+SEG+s], sF1[sb0+SEG+s], sF2[sb0+SEG+s]);
    }

    double part = 0.0;
    if (nA > 0) {
        if (segA < SEG_LAST) {
            part += ((double)fa0 - (double)BnA0)
                  + ((double)fa1 - (double)BnA1)
                  + ((double)fa2 - (double)BnA2);
        } else if (segA == SEG_LAST) {
            g_stop3[0] = __fadd_rn(fa0, sTr[STOP_T * NTAGS + 0]);
            g_stop3[1] = __fadd_rn(fa1, sTr[STOP_T * NTAGS + 1]);
            g_stop3[2] = __fadd_rn(fa2, sTr[STOP_T * NTAGS + 2]);
        }
    }
    if (nB > 0) {
        int segB = segA + 1;
        if (segB < SEG_LAST) {
            part += ((double)fb0 - (double)BnB0)
                  + ((double)fb1 - (double)BnB1)
                  + ((double)fb2 - (double)BnB2);
        } else if (segB == SEG_LAST) {
            g_stop3[0] = __fadd_rn(fb0, sTr[STOP_T * NTAGS + 0]);
            g_stop3[1] = __fadd_rn(fb1, sTr[STOP_T * NTAGS + 1]);
            g_stop3[2] = __fadd_rn(fb2, sTr[STOP_T * NTAGS + 2]);
        }
    }
    part *= (1.0 / 3.0);

#pragma unroll
    for (int o = 16; o > 0; o >>= 1) part += __shfl_down_sync(0xFFFFFFFFu, part, o);
    if (lane == 0) sRD[wid] = part;
    __syncthreads();
    if (tid == 0) {
        double pp = 0.0;
        for (int k = 0; k < 8; ++k) pp += sRD[k];
        g_partB[bid] = pp;
        __threadfence();
        unsigned v = atomicAdd(&g_tick, 1u);
        sLast = (v == (unsigned)(NB - 1));
    }
    __syncthreads();
    if (!sLast) return;
    __threadfence();

    // ================= final epilogue (last block) =================
    double s = 0.0;
    for (int i = tid; i < NB; i += 256) s += g_partB[i];
#pragma unroll
    for (int o = 16; o > 0; o >>= 1) s += __shfl_down_sync(0xFFFFFFFFu, s, o);
    if (lane == 0) sRD[wid] = s;

    double sg = 0.0;
    for (int i = tid; i < NB; i += 256) sg += (double)g_goldB[i];
#pragma unroll
    for (int o = 16; o > 0; o >>= 1) sg += __shfl_down_sync(0xFFFFFFFFu, sg, o);
    if (lane == 0) sRD2[wid] = sg;
    __syncthreads();

    if (tid == 0) {
        double mu = 0.0, goldsum = 0.0;
        for (int k = 0; k < 8; ++k) { mu += sRD[k]; goldsum += sRD2[k]; }

        double b0 = (double)g_stop3[0], b1 = (double)g_stop3[1], b2 = (double)g_stop3[2];
        double m = fmax(fmax(b0, b1), b2);
        double alpha = m + log(exp(b0 - m) + exp(b1 - m) + exp(b2 - m)) + mu;

        int tg0 = tags[0];
        int tgL = tags[T_LEN - 1];
        double gold = goldsum
                    + (double)trans[tg0 * NTAGS + START_T]
                    + (double)feats[tg0]
                    + (double)trans[STOP_T * NTAGS + tgL];
        out[0] = (float)(alpha - gold);

        g_bar = 0;
        g_tick = 0;
    }
}

extern "C" void kernel_launch(void* const* d_in, const int* in_sizes, int n_in,
                              void* d_out, int out_size) {
    const float* feats = nullptr;
    const int*   tags  = nullptr;
    const float* trans = nullptr;
    for (int i = 0; i < n_in; ++i) {
        if (in_sizes[i] == NTAGS * NTAGS)      trans = (const float*)d_in[i];
        else if (in_sizes[i] == T_LEN)         tags  = (const int*)d_in[i];
        else                                   feats = (const float*)d_in[i];
    }
    float* out = (float*)d_out;

    crf_fused<<<NB, 256>>>(feats, tags, trans, out);
}

// round 15
// speedup vs baseline: 1.2531x; 1.2531x over previous
#include <cuda_runtime.h>
#include <math.h>

#define T_LEN   2000000
#define NTAGS   5
#define START_T 3
#define STOP_T  4
#define LN2_D   0.6931471805599453

#define NB      456                   // 3 blocks/SM x 152 SMs — all co-resident
#define CPT     18                    // steps per thread
#define SPB     (256 * CPT)           // 4608 steps per block
#define GPB     (SPB / 4)             // 1152 4-row groups per block
#define NGRP    500000
#define SSTR    19                    // smem stride (odd -> conflict-free)
#define GL_LAST 111111                // 1 + 18*111111 = 1999999 (n=1)
#define SMEM_F  (256 * SSTR)          // floats per feature array
#define DYNSZ   (3 * SMEM_F * 4)      // 58368 bytes dynamic smem

__device__ float    g_Mblk[NB][9];
__device__ int      g_Bblk[NB];
__device__ float    g_goldB[NB];
__device__ double   g_partB[NB];
__device__ float    g_stop3[3];
__device__ unsigned g_bar, g_tick;

__device__ __forceinline__ void renorm9(float* P, int& base) {
    float m = fmaxf(fmaxf(fmaxf(P[0], P[1]), fmaxf(P[2], P[3])),
                    fmaxf(fmaxf(P[4], P[5]), fmaxf(P[6], fmaxf(P[7], P[8]))));
    int e = (int)(__float_as_uint(m) >> 23) - 127;
    float sc = __uint_as_float((unsigned)(127 - e) << 23);
#pragma unroll
    for (int i = 0; i < 9; ++i) P[i] *= sc;
    base += e;
}

__device__ __forceinline__ void mm9(const float* Bm, const float* A, float* C) {
#pragma unroll
    for (int i = 0; i < 3; ++i)
#pragma unroll
        for (int j = 0; j < 3; ++j)
            C[i*3+j] = Bm[i*3+0]*A[0+j] + Bm[i*3+1]*A[3+j] + Bm[i*3+2]*A[6+j];
}

#define MATSTEP(F0, F1, F2) do {                                             \
    float e0 = exp2f(L2E*(F0)), e1 = exp2f(L2E*(F1)), e2 = exp2f(L2E*(F2));  \
    float a0 = e0*Tl[0], a1 = e0*Tl[1], a2 = e0*Tl[2];                       \
    float b0 = e1*Tl[3], b1 = e1*Tl[4], b2 = e1*Tl[5];                       \
    float d0 = e2*Tl[6], d1 = e2*Tl[7], d2 = e2*Tl[8];                       \
    float q0 = a0*P[0] + a1*P[3] + a2*P[6];                                  \
    float q1 = a0*P[1] + a1*P[4] + a2*P[7];                                  \
    float q2 = a0*P[2] + a1*P[5] + a2*P[8];                                  \
    float q3 = b0*P[0] + b1*P[3] + b2*P[6];                                  \
    float q4 = b0*P[1] + b1*P[4] + b2*P[7];                                  \
    float q5 = b0*P[2] + b1*P[5] + b2*P[8];                                  \
    float q6 = d0*P[0] + d1*P[3] + d2*P[6];                                  \
    float q7 = d0*P[1] + d1*P[4] + d2*P[7];                                  \
    float q8 = d0*P[2] + d1*P[5] + d2*P[8];                                  \
    P[0]=q0;P[1]=q1;P[2]=q2;P[3]=q3;P[4]=q4;P[5]=q5;P[6]=q6;P[7]=q7;P[8]=q8; \
} while (0)

#define EMSTEP(F0, F1, F2) do {                                              \
    float f0 = (F0), f1 = (F1), f2 = (F2);                                   \
    float a00=__fadd_rn(fv0,t00), a01=__fadd_rn(fv1,t01), a02=__fadd_rn(fv2,t02);\
    float a10=__fadd_rn(fv0,t10), a11=__fadd_rn(fv1,t11), a12=__fadd_rn(fv2,t12);\
    float a20=__fadd_rn(fv0,t20), a21=__fadd_rn(fv1,t21), a22=__fadd_rn(fv2,t22);\
    float m0=fmaxf(fmaxf(a00,a01),a02);                                      \
    float m1=fmaxf(fmaxf(a10,a11),a12);                                      \
    float m2=fmaxf(fmaxf(a20,a21),a22);                                      \
    float s0=__expf(a00-m0)+__expf(a01-m0)+__expf(a02-m0);                   \
    float s1=__expf(a10-m1)+__expf(a11-m1)+__expf(a12-m1);                   \
    float s2=__expf(a20-m2)+__expf(a21-m2)+__expf(a22-m2);                   \
    fv0=__fadd_rn(__fadd_rn(__logf(s0),m0),f0);                              \
    fv1=__fadd_rn(__fadd_rn(__logf(s1),m1),f1);                              \
    fv2=__fadd_rn(__fadd_rn(__logf(s2),m2),f2);                              \
} while (0)

__global__ void __launch_bounds__(256, 3) crf_fused(
        const float* __restrict__ feats, const int* __restrict__ tags,
        const float* __restrict__ trans, float* __restrict__ out) {
    extern __shared__ float sDyn[];
    float* sF0 = sDyn;
    float* sF1 = sDyn + SMEM_F;
    float* sF2 = sDyn + 2 * SMEM_F;

    __shared__ float  sTr[25];
    __shared__ float  sT9[8][9]; __shared__ int sbT[8];
    __shared__ float  sWE[8][9]; __shared__ int sbWE[8];
    __shared__ float  sEb9[9];   __shared__ int sEbB;
    __shared__ double sRD[8];
    __shared__ double sRD2[8];
    __shared__ float  sRF[8];
    __shared__ bool   sLast;

    const float L2E = 1.4426950408889634f;
    int tid = threadIdx.x, lane = tid & 31, wid = tid >> 5, bid = blockIdx.x;
    if (tid < 25) sTr[tid] = trans[tid];
    __syncthreads();

    float Tl[9];
#pragma unroll
    for (int i = 0; i < 3; ++i)
#pragma unroll
        for (int k = 0; k < 3; ++k)
            Tl[i*3+k] = exp2f(L2E * sTr[i * NTAGS + k]);

    // ================= Phase A: coalesced load -> smem + fused gold =================
    float gold = 0.f;
#pragma unroll
    for (int it = 0; it < 5; ++it) {
        int Gl = it * 256 + tid;
        if (Gl < GPB) {
            int G = bid * GPB + Gl;
            if (G < NGRP) {
                const float4* fp = (const float4*)feats;
                int q = 5 * G + 1;
                float4 v0, v1, v2, v3, v4;
                if (G < NGRP - 1) {
                    v0 = fp[q];     v1 = fp[q + 1]; v2 = fp[q + 2];
                    v3 = fp[q + 3]; v4 = fp[q + 4];
                } else {
                    v0 = fp[q];     v1 = fp[q + 1]; v2 = fp[q + 2]; v3 = fp[q + 3];
                    v4 = make_float4(0.f, 0.f, 0.f, 0.f);
                }
                float w0[4] = {v0.y, v1.z, v2.w, v4.x};
                float w1[4] = {v0.z, v1.w, v3.x, v4.y};
                float w2[4] = {v0.w, v2.x, v3.y, v4.z};

                int4 tg = ((const int4*)tags)[G];
                bool r3v = (4 * G + 4 < T_LEN);
                int tg4 = r3v ? __ldg(&tags[4 * G + 4]) : 0;
                int prev = tg.x, cur;
                cur = tg.y; gold += ((cur==0)?w0[0]:(cur==1)?w1[0]:w2[0]) + sTr[cur*5+prev]; prev = cur;
                cur = tg.z; gold += ((cur==0)?w0[1]:(cur==1)?w1[1]:w2[1]) + sTr[cur*5+prev]; prev = cur;
                cur = tg.w; gold += ((cur==0)?w0[2]:(cur==1)?w1[2]:w2[2]) + sTr[cur*5+prev]; prev = cur;
                if (r3v) {
                    cur = tg4; gold += ((cur==0)?w0[3]:(cur==1)?w1[3]:w2[3]) + sTr[cur*5+prev];
                }
#pragma unroll
                for (int r = 0; r < 4; ++r) {
                    int o = 4 * Gl + r;
                    int ln = o / CPT, s = o - CPT * ln;
                    int a = ln * SSTR + s;
                    sF0[a] = w0[r]; sF1[a] = w1[r]; sF2[a] = w2[r];
                }
            }
        }
    }
#pragma unroll
    for (int o = 16; o > 0; o >>= 1) gold += __shfl_down_sync(0xFFFFFFFFu, gold, o);
    if (lane == 0) sRF[wid] = gold;
    __syncthreads();                           // also publishes sF*
    if (tid == 0) {
        float gg = 0.f;
        for (int k = 0; k < 8; ++k) gg += sRF[k];
        g_goldB[bid] = gg;
    }

    // ================= matrices (CPT steps, smem features) =================
    int w0t = 1 + bid * SPB + tid * CPT;
    int n = T_LEN - w0t; n = n < 0 ? 0 : (n > CPT ? CPT : n);
    int sb0 = tid * SSTR;

    float P[9] = {1.f,0.f,0.f, 0.f,1.f,0.f, 0.f,0.f,1.f};
    int base = 0;
    if (n == CPT) {
#pragma unroll
        for (int s = 0; s < CPT; ++s) {
            MATSTEP(sF0[sb0+s], sF1[sb0+s], sF2[sb0+s]);
            if (s == 5 || s == 11) renorm9(P, base);   // <=7 unrenormed steps, safe
        }
    } else {
        for (int s = 0; s < n; ++s) {
            MATSTEP(sF0[sb0+s], sF1[sb0+s], sF2[sb0+s]);
            if (s == 5 || s == 11) renorm9(P, base);
        }
    }
    renorm9(P, base);

    // warp Kogge-Stone inclusive scan; renorm only at end
#pragma unroll
    for (int s = 1; s < 32; s <<= 1) {
        float A[9];
#pragma unroll
        for (int i = 0; i < 9; ++i) A[i] = __shfl_up_sync(0xFFFFFFFFu, P[i], s);
        int ab = __shfl_up_sync(0xFFFFFFFFu, base, s);
        if (lane >= s) {
            float C[9];
            mm9(P, A, C);
            base += ab;
#pragma unroll
            for (int i = 0; i < 9; ++i) P[i] = C[i];
        }
    }
    renorm9(P, base);
    if (lane == 31) {
#pragma unroll
        for (int i = 0; i < 9; ++i) sT9[wid][i] = P[i];
        sbT[wid] = base;
    }
    __syncthreads();
    if (tid < 8) {
        float E[9] = {1.f,0.f,0.f, 0.f,1.f,0.f, 0.f,0.f,1.f};
        int be = 0;
        for (int k = 0; k < tid; ++k) {
            float Tk[9], C[9];
#pragma unroll
            for (int i = 0; i < 9; ++i) Tk[i] = sT9[k][i];
            mm9(Tk, E, C);
            be += sbT[k];
#pragma unroll
            for (int i = 0; i < 9; ++i) E[i] = C[i];
        }
        renorm9(E, be);
#pragma unroll
        for (int i = 0; i < 9; ++i) sWE[tid][i] = E[i];
        sbWE[tid] = be;
    }
    __syncthreads();

    float Cinc[9]; int bb;
    {
        float WE[9];
#pragma unroll
        for (int i = 0; i < 9; ++i) WE[i] = sWE[wid][i];
        mm9(P, WE, Cinc);
        bb = base + sbWE[wid];
        renorm9(Cinc, bb);
    }
    if (tid == 255) {
#pragma unroll
        for (int i = 0; i < 9; ++i) g_Mblk[bid][i] = Cinc[i];
        g_Bblk[bid] = bb;
    }

    // ================= global barrier (all 456 blocks co-resident) =================
    __syncthreads();
    if (tid == 0) {
        __threadfence();
        atomicAdd(&g_bar, 1u);
        while (*((volatile unsigned*)&g_bar) < (unsigned)NB) __nanosleep(64);
    }
    __syncthreads();
    __threadfence();

    // ===== block-exclusive prefix Eb: block-wide ordered reduction over [0, bid) =====
    {
        float E[9] = {1.f,0.f,0.f, 0.f,1.f,0.f, 0.f,0.f,1.f};
        int be = 0;
#pragma unroll
        for (int k = 0; k < 2; ++k) {
            int i = tid * 2 + k;
            if (i < bid) {
                float M[9], C[9];
#pragma unroll
                for (int j = 0; j < 9; ++j) M[j] = g_Mblk[i][j];
                mm9(M, E, C);
                be += g_Bblk[i];
#pragma unroll
                for (int j = 0; j < 9; ++j) E[j] = C[j];
            }
        }
        renorm9(E, be);
#pragma unroll
        for (int o = 1; o < 32; o <<= 1) {     // shfl_down: received = later segment
            float R[9];
#pragma unroll
            for (int j = 0; j < 9; ++j) R[j] = __shfl_down_sync(0xFFFFFFFFu, E[j], o);
            int rb = __shfl_down_sync(0xFFFFFFFFu, be, o);
            float C[9];
            mm9(R, E, C);
            be += rb;
            renorm9(C, be);
#pragma unroll
            for (int j = 0; j < 9; ++j) E[j] = C[j];
        }
        if (lane == 0) {
#pragma unroll
            for (int j = 0; j < 9; ++j) sT9[wid][j] = E[j];
            sbT[wid] = be;
        }
    }
    __syncthreads();
    if (tid == 0) {
        float E[9] = {1.f,0.f,0.f, 0.f,1.f,0.f, 0.f,0.f,1.f};
        int be = 0;
        for (int w = 0; w < 8; ++w) {
            float Tk[9], C[9];
#pragma unroll
            for (int j = 0; j < 9; ++j) Tk[j] = sT9[w][j];
            mm9(Tk, E, C);
            be += sbT[w];
            renorm9(C, be);
#pragma unroll
            for (int j = 0; j < 9; ++j) E[j] = C[j];
        }
#pragma unroll
        for (int j = 0; j < 9; ++j) sEb9[j] = E[j];
        sEbB = be;
    }
    __syncthreads();

    // ================= boundaries (registers) + emulation walk =================
    float v00 = sTr[0*NTAGS+START_T] + __ldg(&feats[0]);
    float v01 = sTr[1*NTAGS+START_T] + __ldg(&feats[1]);
    float v02 = sTr[2*NTAGS+START_T] + __ldg(&feats[2]);
    float c0f = fmaxf(fmaxf(v00, v01), v02);
    double c0d = (double)c0f;
    float u0[3] = {__expf(v00-c0f), __expf(v01-c0f), __expf(v02-c0f)};

    float Eb[9]; int bE = sEbB;
#pragma unroll
    for (int j = 0; j < 9; ++j) Eb[j] = sEb9[j];

    float M9[9]; int bM = bb + bE;
    mm9(Cinc, Eb, M9);
    renorm9(M9, bM);
    double tB = (double)bM * LN2_D + c0d;
    float Bn0 = (float)((double)__logf(M9[0]*u0[0] + M9[1]*u0[1] + M9[2]*u0[2]) + tB);
    float Bn1 = (float)((double)__logf(M9[3]*u0[0] + M9[4]*u0[1] + M9[5]*u0[2]) + tB);
    float Bn2 = (float)((double)__logf(M9[6]*u0[0] + M9[7]*u0[1] + M9[8]*u0[2]) + tB);

    float A0 = __shfl_up_sync(0xFFFFFFFFu, Bn0, 1);
    float A1 = __shfl_up_sync(0xFFFFFFFFu, Bn1, 1);
    float A2 = __shfl_up_sync(0xFFFFFFFFu, Bn2, 1);
    if (lane == 0) {
        if (bid == 0 && tid == 0) {
            A0 = v00; A1 = v01; A2 = v02;
        } else {
            float EX[9]; int bx;
            if (wid == 0) {
#pragma unroll
                for (int j = 0; j < 9; ++j) EX[j] = Eb[j];
                bx = bE;
            } else {
                float W[9];
#pragma unroll
                for (int j = 0; j < 9; ++j) W[j] = sWE[wid][j];
                mm9(W, Eb, EX);
                bx = sbWE[wid] + bE;
                renorm9(EX, bx);
            }
            double tX = (double)bx * LN2_D + c0d;
            A0 = (float)((double)__logf(EX[0]*u0[0] + EX[1]*u0[1] + EX[2]*u0[2]) + tX);
            A1 = (float)((double)__logf(EX[3]*u0[0] + EX[4]*u0[1] + EX[5]*u0[2]) + tX);
            A2 = (float)((double)__logf(EX[6]*u0[0] + EX[7]*u0[1] + EX[8]*u0[2]) + tX);
        }
    }

    double part = 0.0;
    int gl = bid * 256 + tid;
    if (n > 0) {
        float t00 = sTr[0],  t01 = sTr[1],  t02 = sTr[2];
        float t10 = sTr[5],  t11 = sTr[6],  t12 = sTr[7];
        float t20 = sTr[10], t21 = sTr[11], t22 = sTr[12];
        float fv0 = A0, fv1 = A1, fv2 = A2;
        if (n == CPT) {
#pragma unroll
            for (int s = 0; s < CPT; ++s) EMSTEP(sF0[sb0+s], sF1[sb0+s], sF2[sb0+s]);
        } else {
            for (int s = 0; s < n; ++s) EMSTEP(sF0[sb0+s], sF1[sb0+s], sF2[sb0+s]);
        }
        if (gl < GL_LAST) {
            part = (((double)fv0 - (double)Bn0)
                  + ((double)fv1 - (double)Bn1)
                  + ((double)fv2 - (double)Bn2)) / 3.0;
        } else if (gl == GL_LAST) {
            g_stop3[0] = __fadd_rn(fv0, sTr[STOP_T * NTAGS + 0]);
            g_stop3[1] = __fadd_rn(fv1, sTr[STOP_T * NTAGS + 1]);
            g_stop3[2] = __fadd_rn(fv2, sTr[STOP_T * NTAGS + 2]);
        }
    }

#pragma unroll
    for (int o = 16; o > 0; o >>= 1) part += __shfl_down_sync(0xFFFFFFFFu, part, o);
    if (lane == 0) sRD[wid] = part;
    __syncthreads();
    if (tid == 0) {
        double pp = 0.0;
        for (int k = 0; k < 8; ++k) pp += sRD[k];
        g_partB[bid] = pp;
        __threadfence();
        unsigned v = atomicAdd(&g_tick, 1u);
        sLast = (v == (unsigned)(NB - 1));
    }
    __syncthreads();
    if (!sLast) return;
    __threadfence();

    // ================= final epilogue (last block) =================
    double s = 0.0;
    for (int i = tid; i < NB; i += 256) s += g_partB[i];
#pragma unroll
    for (int o = 16; o > 0; o >>= 1) s += __shfl_down_sync(0xFFFFFFFFu, s, o);
    if (lane == 0) sRD[wid] = s;

    double sg = 0.0;
    for (int i = tid; i < NB; i += 256) sg += (double)g_goldB[i];
#pragma unroll
    for (int o = 16; o > 0; o >>= 1) sg += __shfl_down_sync(0xFFFFFFFFu, sg, o);
    if (lane == 0) sRD2[wid] = sg;
    __syncthreads();

    if (tid == 0) {
        double mu = 0.0, goldsum = 0.0;
        for (int k = 0; k < 8; ++k) { mu += sRD[k]; goldsum += sRD2[k]; }

        double b0 = (double)g_stop3[0], b1 = (double)g_stop3[1], b2 = (double)g_stop3[2];
        double m = fmax(fmax(b0, b1), b2);
        double alpha = m + log(exp(b0 - m) + exp(b1 - m) + exp(b2 - m)) + mu;

        int tg0 = tags[0];
        int tgL = tags[T_LEN - 1];
        double gold = goldsum
                    + (double)trans[tg0 * NTAGS + START_T]
                    + (double)feats[tg0]
                    + (double)trans[STOP_T * NTAGS + tgL];
        out[0] = (float)(alpha - gold);

        g_bar = 0;
        g_tick = 0;
    }
}

extern "C" void kernel_launch(void* const* d_in, const int* in_sizes, int n_in,
                              void* d_out, int out_size) {
    const float* feats = nullptr;
    const int*   tags  = nullptr;
    const float* trans = nullptr;
    for (int i = 0; i < n_in; ++i) {
        if (in_sizes[i] == NTAGS * NTAGS)      trans = (const float*)d_in[i];
        else if (in_sizes[i] == T_LEN)         tags  = (const int*)d_in[i];
        else                                   feats = (const float*)d_in[i];
    }
    float* out = (float*)d_out;

    static bool attr_set = false;
    if (!attr_set) {
        cudaFuncSetAttribute(crf_fused, cudaFuncAttributeMaxDynamicSharedMemorySize, DYNSZ);
        attr_set = true;
    }
    crf_fused<<<NB, 256, DYNSZ>>>(feats, tags, trans, out);
}

// round 16
// speedup vs baseline: 1.3160x; 1.0502x over previous
#include <cuda_runtime.h>
#include <math.h>

#define T_LEN   2000000
#define NTAGS   5
#define START_T 3
#define STOP_T  4
#define LN2_D   0.6931471805599453

#define NB      304                   // 2 blocks/SM x 152 SMs — all co-resident
#define CPT     27                    // steps per thread
#define SPB     (256 * CPT)           // 6912 steps per block
#define GPB     (SPB / 4)             // 1728 4-row groups per block
#define NGRP    500000
#define SSTR    29                    // smem stride (odd -> conflict-free)
#define GL_LAST 74074                 // 1 + 27*74074 = 1999999 (n=1)
#define SMEM_F  (256 * SSTR)          // floats per feature array
#define DYNSZ   (3 * SMEM_F * 4)      // 89088 bytes dynamic smem

__device__ float    g_Mblk[NB][9];
__device__ int      g_Bblk[NB];
__device__ float    g_goldB[NB];
__device__ double   g_partB[NB];
__device__ float    g_stop3[3];
__device__ unsigned g_bar, g_tick;

__device__ __forceinline__ void renorm9(float* P, int& base) {
    float m = fmaxf(fmaxf(fmaxf(P[0], P[1]), fmaxf(P[2], P[3])),
                    fmaxf(fmaxf(P[4], P[5]), fmaxf(P[6], fmaxf(P[7], P[8]))));
    int e = (int)(__float_as_uint(m) >> 23) - 127;
    float sc = __uint_as_float((unsigned)(127 - e) << 23);
#pragma unroll
    for (int i = 0; i < 9; ++i) P[i] *= sc;
    base += e;
}

__device__ __forceinline__ void mm9(const float* Bm, const float* A, float* C) {
#pragma unroll
    for (int i = 0; i < 3; ++i)
#pragma unroll
        for (int j = 0; j < 3; ++j)
            C[i*3+j] = Bm[i*3+0]*A[0+j] + Bm[i*3+1]*A[3+j] + Bm[i*3+2]*A[6+j];
}

#define MATSTEP(F0, F1, F2) do {                                             \
    float e0 = exp2f(L2E*(F0)), e1 = exp2f(L2E*(F1)), e2 = exp2f(L2E*(F2));  \
    float a0 = e0*Tl[0], a1 = e0*Tl[1], a2 = e0*Tl[2];                       \
    float b0 = e1*Tl[3], b1 = e1*Tl[4], b2 = e1*Tl[5];                       \
    float d0 = e2*Tl[6], d1 = e2*Tl[7], d2 = e2*Tl[8];                       \
    float q0 = a0*P[0] + a1*P[3] + a2*P[6];                                  \
    float q1 = a0*P[1] + a1*P[4] + a2*P[7];                                  \
    float q2 = a0*P[2] + a1*P[5] + a2*P[8];                                  \
    float q3 = b0*P[0] + b1*P[3] + b2*P[6];                                  \
    float q4 = b0*P[1] + b1*P[4] + b2*P[7];                                  \
    float q5 = b0*P[2] + b1*P[5] + b2*P[8];                                  \
    float q6 = d0*P[0] + d1*P[3] + d2*P[6];                                  \
    float q7 = d0*P[1] + d1*P[4] + d2*P[7];                                  \
    float q8 = d0*P[2] + d1*P[5] + d2*P[8];                                  \
    P[0]=q0;P[1]=q1;P[2]=q2;P[3]=q3;P[4]=q4;P[5]=q5;P[6]=q6;P[7]=q7;P[8]=q8; \
} while (0)

#define EMSTEP(F0, F1, F2) do {                                              \
    float f0 = (F0), f1 = (F1), f2 = (F2);                                   \
    float a00=__fadd_rn(fv0,t00), a01=__fadd_rn(fv1,t01), a02=__fadd_rn(fv2,t02);\
    float a10=__fadd_rn(fv0,t10), a11=__fadd_rn(fv1,t11), a12=__fadd_rn(fv2,t12);\
    float a20=__fadd_rn(fv0,t20), a21=__fadd_rn(fv1,t21), a22=__fadd_rn(fv2,t22);\
    float m0=fmaxf(fmaxf(a00,a01),a02);                                      \
    float m1=fmaxf(fmaxf(a10,a11),a12);                                      \
    float m2=fmaxf(fmaxf(a20,a21),a22);                                      \
    float s0=__expf(a00-m0)+__expf(a01-m0)+__expf(a02-m0);                   \
    float s1=__expf(a10-m1)+__expf(a11-m1)+__expf(a12-m1);                   \
    float s2=__expf(a20-m2)+__expf(a21-m2)+__expf(a22-m2);                   \
    fv0=__fadd_rn(__fadd_rn(__logf(s0),m0),f0);                              \
    fv1=__fadd_rn(__fadd_rn(__logf(s1),m1),f1);                              \
    fv2=__fadd_rn(__fadd_rn(__logf(s2),m2),f2);                              \
} while (0)

__global__ void __launch_bounds__(256, 2) crf_fused(
        const float* __restrict__ feats, const int* __restrict__ tags,
        const float* __restrict__ trans, float* __restrict__ out) {
    extern __shared__ float sDyn[];
    float* sF0 = sDyn;
    float* sF1 = sDyn + SMEM_F;
    float* sF2 = sDyn + 2 * SMEM_F;

    __shared__ float  sTr[25];
    __shared__ float  sT9[8][9]; __shared__ int sbT[8];
    __shared__ float  sWE[8][9]; __shared__ int sbWE[8];
    __shared__ float  sEb9[9];   __shared__ int sEbB;
    __shared__ double sRD[8];
    __shared__ double sRD2[8];
    __shared__ float  sRF[8];
    __shared__ bool   sLast;

    const float L2E = 1.4426950408889634f;
    int tid = threadIdx.x, lane = tid & 31, wid = tid >> 5, bid = blockIdx.x;
    if (tid < 25) sTr[tid] = trans[tid];
    __syncthreads();

    float Tl[9];
#pragma unroll
    for (int i = 0; i < 3; ++i)
#pragma unroll
        for (int k = 0; k < 3; ++k)
            Tl[i*3+k] = exp2f(L2E * sTr[i * NTAGS + k]);

    // ================= Phase A: coalesced load -> smem + fused gold =================
    float gold = 0.f;
#pragma unroll
    for (int it = 0; it < 7; ++it) {
        int Gl = it * 256 + tid;
        if (Gl < GPB) {
            int G = bid * GPB + Gl;
            if (G < NGRP) {
                const float4* fp = (const float4*)feats;
                int q = 5 * G + 1;
                float4 v0, v1, v2, v3, v4;
                if (G < NGRP - 1) {
                    v0 = fp[q];     v1 = fp[q + 1]; v2 = fp[q + 2];
                    v3 = fp[q + 3]; v4 = fp[q + 4];
                } else {
                    v0 = fp[q];     v1 = fp[q + 1]; v2 = fp[q + 2]; v3 = fp[q + 3];
                    v4 = make_float4(0.f, 0.f, 0.f, 0.f);
                }
                float w0[4] = {v0.y, v1.z, v2.w, v4.x};
                float w1[4] = {v0.z, v1.w, v3.x, v4.y};
                float w2[4] = {v0.w, v2.x, v3.y, v4.z};

                int4 tg = ((const int4*)tags)[G];
                bool r3v = (4 * G + 4 < T_LEN);
                int tg4 = r3v ? __ldg(&tags[4 * G + 4]) : 0;
                int prev = tg.x, cur;
                cur = tg.y; gold += ((cur==0)?w0[0]:(cur==1)?w1[0]:w2[0]) + sTr[cur*5+prev]; prev = cur;
                cur = tg.z; gold += ((cur==0)?w0[1]:(cur==1)?w1[1]:w2[1]) + sTr[cur*5+prev]; prev = cur;
                cur = tg.w; gold += ((cur==0)?w0[2]:(cur==1)?w1[2]:w2[2]) + sTr[cur*5+prev]; prev = cur;
                if (r3v) {
                    cur = tg4; gold += ((cur==0)?w0[3]:(cur==1)?w1[3]:w2[3]) + sTr[cur*5+prev];
                }
#pragma unroll
                for (int r = 0; r < 4; ++r) {
                    int o = 4 * Gl + r;
                    int ln = o / CPT, s = o - CPT * ln;
                    int a = ln * SSTR + s;
                    sF0[a] = w0[r]; sF1[a] = w1[r]; sF2[a] = w2[r];
                }
            }
        }
    }
#pragma unroll
    for (int o = 16; o > 0; o >>= 1) gold += __shfl_down_sync(0xFFFFFFFFu, gold, o);
    if (lane == 0) sRF[wid] = gold;
    __syncthreads();                           // also publishes sF*
    if (tid == 0) {
        float gg = 0.f;
        for (int k = 0; k < 8; ++k) gg += sRF[k];
        g_goldB[bid] = gg;
    }

    // ================= matrices (CPT steps, smem features) =================
    int w0t = 1 + bid * SPB + tid * CPT;
    int n = T_LEN - w0t; n = n < 0 ? 0 : (n > CPT ? CPT : n);
    int sb0 = tid * SSTR;

    float P[9] = {1.f,0.f,0.f, 0.f,1.f,0.f, 0.f,0.f,1.f};
    int base = 0;
    if (n == CPT) {
#pragma unroll
        for (int s = 0; s < CPT; ++s) {
            MATSTEP(sF0[sb0+s], sF1[sb0+s], sF2[sb0+s]);
            if ((s % 6) == 5) renorm9(P, base);        // <=6 unrenormed steps, safe
        }
    } else {
        for (int s = 0; s < n; ++s) {
            MATSTEP(sF0[sb0+s], sF1[sb0+s], sF2[sb0+s]);
            if ((s % 6) == 5) renorm9(P, base);
        }
    }
    renorm9(P, base);

    // warp Kogge-Stone inclusive scan; renorm only at end
#pragma unroll
    for (int s = 1; s < 32; s <<= 1) {
        float A[9];
#pragma unroll
        for (int i = 0; i < 9; ++i) A[i] = __shfl_up_sync(0xFFFFFFFFu, P[i], s);
        int ab = __shfl_up_sync(0xFFFFFFFFu, base, s);
        if (lane >= s) {
            float C[9];
            mm9(P, A, C);
            base += ab;
#pragma unroll
            for (int i = 0; i < 9; ++i) P[i] = C[i];
        }
    }
    renorm9(P, base);
    if (lane == 31) {
#pragma unroll
        for (int i = 0; i < 9; ++i) sT9[wid][i] = P[i];
        sbT[wid] = base;
    }
    __syncthreads();
    if (tid < 8) {
        float E[9] = {1.f,0.f,0.f, 0.f,1.f,0.f, 0.f,0.f,1.f};
        int be = 0;
        for (int k = 0; k < tid; ++k) {
            float Tk[9], C[9];
#pragma unroll
            for (int i = 0; i < 9; ++i) Tk[i] = sT9[k][i];
            mm9(Tk, E, C);
            be += sbT[k];
#pragma unroll
            for (int i = 0; i < 9; ++i) E[i] = C[i];
        }
        renorm9(E, be);
#pragma unroll
        for (int i = 0; i < 9; ++i) sWE[tid][i] = E[i];
        sbWE[tid] = be;
    }
    __syncthreads();

    float Cinc[9]; int bb;
    {
        float WE[9];
#pragma unroll
        for (int i = 0; i < 9; ++i) WE[i] = sWE[wid][i];
        mm9(P, WE, Cinc);
        bb = base + sbWE[wid];
        renorm9(Cinc, bb);
    }
    if (tid == 255) {
#pragma unroll
        for (int i = 0; i < 9; ++i) g_Mblk[bid][i] = Cinc[i];
        g_Bblk[bid] = bb;
    }

    // ================= global barrier (all 304 blocks co-resident) =================
    __syncthreads();
    if (tid == 0) {
        __threadfence();
        atomicAdd(&g_bar, 1u);
        while (*((volatile unsigned*)&g_bar) < (unsigned)NB) __nanosleep(64);
    }
    __syncthreads();
    __threadfence();

    // ===== block-exclusive prefix Eb: block-wide ordered reduction over [0, bid) =====
    {
        float E[9] = {1.f,0.f,0.f, 0.f,1.f,0.f, 0.f,0.f,1.f};
        int be = 0;
#pragma unroll
        for (int k = 0; k < 2; ++k) {
            int i = tid * 2 + k;
            if (i < bid) {
                float M[9], C[9];
#pragma unroll
                for (int j = 0; j < 9; ++j) M[j] = g_Mblk[i][j];
                mm9(M, E, C);
                be += g_Bblk[i];
#pragma unroll
                for (int j = 0; j < 9; ++j) E[j] = C[j];
            }
        }
        renorm9(E, be);
#pragma unroll
        for (int o = 1; o < 32; o <<= 1) {     // shfl_down: received = later segment
            float R[9];
#pragma unroll
            for (int j = 0; j < 9; ++j) R[j] = __shfl_down_sync(0xFFFFFFFFu, E[j], o);
            int rb = __shfl_down_sync(0xFFFFFFFFu, be, o);
            float C[9];
            mm9(R, E, C);
            be += rb;
            renorm9(C, be);
#pragma unroll
            for (int j = 0; j < 9; ++j) E[j] = C[j];
        }
        if (lane == 0) {
#pragma unroll
            for (int j = 0; j < 9; ++j) sT9[wid][j] = E[j];
            sbT[wid] = be;
        }
    }
    __syncthreads();
    if (tid == 0) {
        float E[9] = {1.f,0.f,0.f, 0.f,1.f,0.f, 0.f,0.f,1.f};
        int be = 0;
        for (int w = 0; w < 8; ++w) {
            float Tk[9], C[9];
#pragma unroll
            for (int j = 0; j < 9; ++j) Tk[j] = sT9[w][j];
            mm9(Tk, E, C);
            be += sbT[w];
            renorm9(C, be);
#pragma unroll
            for (int j = 0; j < 9; ++j) E[j] = C[j];
        }
#pragma unroll
        for (int j = 0; j < 9; ++j) sEb9[j] = E[j];
        sEbB = be;
    }
    __syncthreads();

    // ================= boundaries (registers) + emulation walk =================
    float v00 = sTr[0*NTAGS+START_T] + __ldg(&feats[0]);
    float v01 = sTr[1*NTAGS+START_T] + __ldg(&feats[1]);
    float v02 = sTr[2*NTAGS+START_T] + __ldg(&feats[2]);
    float c0f = fmaxf(fmaxf(v00, v01), v02);
    double c0d = (double)c0f;
    float u0[3] = {__expf(v00-c0f), __expf(v01-c0f), __expf(v02-c0f)};

    float Eb[9]; int bE = sEbB;
#pragma unroll
    for (int j = 0; j < 9; ++j) Eb[j] = sEb9[j];

    float M9[9]; int bM = bb + bE;
    mm9(Cinc, Eb, M9);
    renorm9(M9, bM);
    double tB = (double)bM * LN2_D + c0d;
    float Bn0 = (float)((double)__logf(M9[0]*u0[0] + M9[1]*u0[1] + M9[2]*u0[2]) + tB);
    float Bn1 = (float)((double)__logf(M9[3]*u0[0] + M9[4]*u0[1] + M9[5]*u0[2]) + tB);
    float Bn2 = (float)((double)__logf(M9[6]*u0[0] + M9[7]*u0[1] + M9[8]*u0[2]) + tB);

    float A0 = __shfl_up_sync(0xFFFFFFFFu, Bn0, 1);
    float A1 = __shfl_up_sync(0xFFFFFFFFu, Bn1, 1);
    float A2 = __shfl_up_sync(0xFFFFFFFFu, Bn2, 1);
    if (lane == 0) {
        if (bid == 0 && tid == 0) {
            A0 = v00; A1 = v01; A2 = v02;
        } else {
            float EX[9]; int bx;
            if (wid == 0) {
#pragma unroll
                for (int j = 0; j < 9; ++j) EX[j] = Eb[j];
                bx = bE;
            } else {
                float W[9];
#pragma unroll
                for (int j = 0; j < 9; ++j) W[j] = sWE[wid][j];
                mm9(W, Eb, EX);
                bx = sbWE[wid] + bE;
                renorm9(EX, bx);
            }
            double tX = (double)bx * LN2_D + c0d;
            A0 = (float)((double)__logf(EX[0]*u0[0] + EX[1]*u0[1] + EX[2]*u0[2]) + tX);
            A1 = (float)((double)__logf(EX[3]*u0[0] + EX[4]*u0[1] + EX[5]*u0[2]) + tX);
            A2 = (float)((double)__logf(EX[6]*u0[0] + EX[7]*u0[1] + EX[8]*u0[2]) + tX);
        }
    }

    double part = 0.0;
    int gl = bid * 256 + tid;
    if (n > 0) {
        float t00 = sTr[0],  t01 = sTr[1],  t02 = sTr[2];
        float t10 = sTr[5],  t11 = sTr[6],  t12 = sTr[7];
        float t20 = sTr[10], t21 = sTr[11], t22 = sTr[12];
        float fv0 = A0, fv1 = A1, fv2 = A2;
        if (n == CPT) {
#pragma unroll
            for (int s = 0; s < CPT; ++s) EMSTEP(sF0[sb0+s], sF1[sb0+s], sF2[sb0+s]);
        } else {
            for (int s = 0; s < n; ++s) EMSTEP(sF0[sb0+s], sF1[sb0+s], sF2[sb0+s]);
        }
        if (gl < GL_LAST) {
            part = (((double)fv0 - (double)Bn0)
                  + ((double)fv1 - (double)Bn1)
                  + ((double)fv2 - (double)Bn2)) / 3.0;
        } else if (gl == GL_LAST) {
            g_stop3[0] = __fadd_rn(fv0, sTr[STOP_T * NTAGS + 0]);
            g_stop3[1] = __fadd_rn(fv1, sTr[STOP_T * NTAGS + 1]);
            g_stop3[2] = __fadd_rn(fv2, sTr[STOP_T * NTAGS + 2]);
        }
    }

#pragma unroll
    for (int o = 16; o > 0; o >>= 1) part += __shfl_down_sync(0xFFFFFFFFu, part, o);
    if (lane == 0) sRD[wid] = part;
    __syncthreads();
    if (tid == 0) {
        double pp = 0.0;
        for (int k = 0; k < 8; ++k) pp += sRD[k];
        g_partB[bid] = pp;
        __threadfence();
        unsigned v = atomicAdd(&g_tick, 1u);
        sLast = (v == (unsigned)(NB - 1));
    }
    __syncthreads();
    if (!sLast) return;
    __threadfence();

    // ================= final epilogue (last block) =================
    double s = 0.0;
    for (int i = tid; i < NB; i += 256) s += g_partB[i];
#pragma unroll
    for (int o = 16; o > 0; o >>= 1) s += __shfl_down_sync(0xFFFFFFFFu, s, o);
    if (lane == 0) sRD[wid] = s;

    double sg = 0.0;
    for (int i = tid; i < NB; i += 256) sg += (double)g_goldB[i];
#pragma unroll
    for (int o = 16; o > 0; o >>= 1) sg += __shfl_down_sync(0xFFFFFFFFu, sg, o);
    if (lane == 0) sRD2[wid] = sg;
    __syncthreads();

    if (tid == 0) {
        double mu = 0.0, goldsum = 0.0;
        for (int k = 0; k < 8; ++k) { mu += sRD[k]; goldsum += sRD2[k]; }

        double b0 = (double)g_stop3[0], b1 = (double)g_stop3[1], b2 = (double)g_stop3[2];
        double m = fmax(fmax(b0, b1), b2);
        double alpha = m + log(exp(b0 - m) + exp(b1 - m) + exp(b2 - m)) + mu;

        int tg0 = tags[0];
        int tgL = tags[T_LEN - 1];
        double gold = goldsum
                    + (double)trans[tg0 * NTAGS + START_T]
                    + (double)feats[tg0]
                    + (double)trans[STOP_T * NTAGS + tgL];
        out[0] = (float)(alpha - gold);

        g_bar = 0;
        g_tick = 0;
    }
}

extern "C" void kernel_launch(void* const* d_in, const int* in_sizes, int n_in,
                              void* d_out, int out_size) {
    const float* feats = nullptr;
    const int*   tags  = nullptr;
    const float* trans = nullptr;
    for (int i = 0; i < n_in; ++i) {
        if (in_sizes[i] == NTAGS * NTAGS)      trans = (const float*)d_in[i];
        else if (in_sizes[i] == T_LEN)         tags  = (const int*)d_in[i];
        else                                   feats = (const float*)d_in[i];
    }
    float* out = (float*)d_out;

    static bool attr_set = false;
    if (!attr_set) {
        cudaFuncSetAttribute(crf_fused, cudaFuncAttributeMaxDynamicSharedMemorySize, DYNSZ);
        attr_set = true;
    }
    crf_fused<<<NB, 256, DYNSZ>>>(feats, tags, trans, out);
}